// round 11
// baseline (speedup 1.0000x reference)
#include <cuda_runtime.h>
#include <cuda_fp16.h>
#include <math.h>

#define BS 32
#define NSAMP 64000
#define NTOT (BS*NSAMP)
#define TPB 128
#define BLK 16                 // XLA ReduceWindowRewriter base_length
#define NB1 (NSAMP/BLK)        // 4000 level-1 blocks per row
#define NB2 (NB1/BLK)          // 250 level-2 blocks
#define NB2P 256               // padded to multiple of 16
#define NB3 (NB2P/BLK)         // 16
#define HSTR 66                // smem h-row stride in halves (conflict-free, 4B-aligned)

__device__ float g_off1[BS*NB1]; // exclusive offset for each level-1 block

typedef unsigned long long u64;

__device__ __forceinline__ float ex2f(float x){ float r; asm("ex2.approx.f32 %0, %1;":"=f"(r):"f"(x)); return r; }
__device__ __forceinline__ float lg2f(float x){ float r; asm("lg2.approx.f32 %0, %1;":"=f"(r):"f"(x)); return r; }

// ---- packed f32x2 helpers ----
__device__ __forceinline__ u64 pack2(float lo, float hi){ u64 r; asm("mov.b64 %0, {%1,%2};":"=l"(r):"f"(lo),"f"(hi)); return r; }
__device__ __forceinline__ void unpack2(u64 v, float& lo, float& hi){ asm("mov.b64 {%0,%1}, %2;":"=f"(lo),"=f"(hi):"l"(v)); }
__device__ __forceinline__ u64 fma2(u64 a,u64 b,u64 c){ u64 r; asm("fma.rn.f32x2 %0,%1,%2,%3;":"=l"(r):"l"(a),"l"(b),"l"(c)); return r; }
__device__ __forceinline__ u64 mul2(u64 a,u64 b){ u64 r; asm("mul.rn.f32x2 %0,%1,%2;":"=l"(r):"l"(a),"l"(b)); return r; }
__device__ __forceinline__ u64 add2(u64 a,u64 b){ u64 r; asm("add.rn.f32x2 %0,%1,%2;":"=l"(r):"l"(a),"l"(b)); return r; }

// 2*sigmoid(x)^ln(10) + 1e-7
__device__ __forceinline__ float hfun(float x){
    float e = ex2f(-1.4426950408889634f * x);
    float u = lg2f(1.0f + e);
    return fmaf(2.0f, ex2f(-2.3025850929940457f * u), 1e-7f);
}

// increment: fast-math (arcp) form
__device__ __forceinline__ float incr(float f){
    const float RINV = 1.0f / 44100.0f;
    return __fmul_rn(__fmul_rn(6.283185307179586f, f), RINV);
}

// ---------------------------------------------------------------------------
// Fused scan kernel (unchanged): S1 -> I2 -> I3 -> O4 -> off1, bit-exact.
// ---------------------------------------------------------------------------
__global__ void __launch_bounds__(512) scan_kernel(const float* __restrict__ f0){
    __shared__ float sI2[NB1];
    __shared__ float sI3[NB2P];
    __shared__ float sO4[NB3];
    const int row = blockIdx.x, tid = threadIdx.x;
    const float* fr = f0 + (size_t)row * NSAMP;

    for (int j = tid; j < NB1; j += 512){
        const float4* fp = (const float4*)(fr + (size_t)j * BLK);
        float acc = 0.0f;
        #pragma unroll
        for (int i = 0; i < BLK/4; i++){
            float4 v = fp[i];
            float d0 = incr(v.x), d1 = incr(v.y), d2 = incr(v.z), d3 = incr(v.w);
            acc = (i == 0) ? d0 : __fadd_rn(acc, d0);
            acc = __fadd_rn(acc, d1);
            acc = __fadd_rn(acc, d2);
            acc = __fadd_rn(acc, d3);
        }
        sI2[j] = acc;
    }
    __syncthreads();

    if (tid < NB2){
        int b = tid * BLK;
        float acc = sI2[b];
        #pragma unroll
        for (int i = 1; i < BLK; i++){ acc = __fadd_rn(acc, sI2[b+i]); sI2[b+i] = acc; }
    }
    __syncthreads();

    if (tid < NB3){
        int b = tid * BLK;
        float acc = 0.0f;
        #pragma unroll
        for (int i = 0; i < BLK; i++){
            int m = b + i;
            float s2 = (m < NB2) ? sI2[m*BLK + (BLK-1)] : 0.0f;
            acc = (i == 0) ? s2 : __fadd_rn(acc, s2);
            sI3[m] = acc;
        }
    }
    __syncthreads();

    if (tid == 0){
        float acc = 0.0f;
        #pragma unroll
        for (int p = 0; p < NB3; p++){
            float s3 = sI3[p*BLK + (BLK-1)];
            acc = (p == 0) ? s3 : __fadd_rn(acc, s3);
            sO4[p] = acc;
        }
    }
    __syncthreads();

    float* off1 = g_off1 + row * NB1;
    for (int j = tid; j < NB1; j += 512){
        float v;
        if (j == 0) v = 0.0f;
        else {
            int jm = j - 1, q = jm >> 4;
            float o3e;
            if (q == 0) o3e = 0.0f;
            else {
                int qm = q - 1, p = qm >> 4;
                float o4e = (p == 0) ? 0.0f : sO4[p-1];
                o3e = __fadd_rn(o4e, sI3[qm]);
            }
            v = __fadd_rn(o3e, sI2[jm]);
        }
        off1[j] = v;
    }
}

// ---------------------------------------------------------------------------
// Oscillator: fp16 h-store (smem 34->18KB) + forced 8 CTAs/SM (occ 36->50%).
// Staging: float4 coalesced loads, fused hfun, incremental (s,j) index walk.
// ---------------------------------------------------------------------------
__global__ void __launch_bounds__(TPB, 8) osc_kernel(
    const float* __restrict__ f0,
    const float* __restrict__ amps,
    const float* __restrict__ phase,
    float* __restrict__ out)
{
    __shared__ __half sHh[TPB * HSTR];  // h[k] at [s*HSTR + (k-1)], k=1..64
    __shared__ float  sTA[TPB];
    __shared__ float  sD[TPB];
    __shared__ float  sOFF[TPB / BLK];
    const int tid    = threadIdx.x;
    const int nchunk = NSAMP / TPB;
    const int b      = blockIdx.x / nchunk;
    const int t0     = (blockIdx.x % nchunk) * TPB;
    const int sbase  = b * NSAMP + t0;

    {   // float4 staging with fused hfun -> fp16 smem.
        // element index e = 4*i decomposed as (s, j) and walked incrementally.
        const float4* gsrc = (const float4*)(amps + (size_t)sbase * 65);
        int s = (4 * tid) / 65;
        int j = (4 * tid) - 65 * s;
        for (int i = tid; i < TPB * 65 / 4; i += TPB){
            float4 v = gsrc[i];
            float h0 = hfun(v.x), h1 = hfun(v.y), h2 = hfun(v.z), h3 = hfun(v.w);
            int ss = s, jj = j;
            // elem 0
            if (jj == 0) sTA[ss] = h0; else sHh[ss*HSTR + jj - 1] = __float2half_rn(h0);
            if (++jj == 65){ jj = 0; ++ss; }
            // elem 1
            if (jj == 0) sTA[ss] = h1; else sHh[ss*HSTR + jj - 1] = __float2half_rn(h1);
            if (++jj == 65){ jj = 0; ++ss; }
            // elem 2
            if (jj == 0) sTA[ss] = h2; else sHh[ss*HSTR + jj - 1] = __float2half_rn(h2);
            if (++jj == 65){ jj = 0; ++ss; }
            // elem 3
            if (jj == 0) sTA[ss] = h3; else sHh[ss*HSTR + jj - 1] = __float2half_rn(h3);
            // advance by 512 elements: +57 mod 65, s += 7 (+1 on wrap)
            j += 57; s += 7;
            if (j >= 65){ j -= 65; s += 1; }
        }
    }
    const int idx   = sbase + tid;
    const float f0v = f0[idx];
    sD[tid] = incr(f0v);
    if (tid < TPB / BLK) sOFF[tid] = g_off1[(sbase >> 4) + tid];
    __syncthreads();

    // bit-exact omega/theta (within-16 ascending fold + one offset add)
    const int g = tid >> 4, i15 = tid & 15;
    float inc = sD[g * BLK];
    for (int i = 1; i <= i15; ++i) inc = __fadd_rn(inc, sD[g * BLK + i]);
    const float omega = __fadd_rn(sOFF[g], inc);
    const float theta = __fadd_rn(omega, phase[b]);

    // accurate sincos(theta): mod-pi in double
    const double thd = (double)theta;
    const double qd  = rint(thd * 0.31830988618379067154);
    const int    q   = (int)qd;
    const double rd  = fma(-3.14159265358979323846, qd, thd);
    const float  r   = (float)rd;
    const float  rl  = (float)(rd - (double)r);

    const float r2 = r * r;
    float p = -2.5052108385441718e-8f;
    p = fmaf(p, r2,  2.7557319223985893e-6f);
    p = fmaf(p, r2, -1.9841269841269841e-4f);
    p = fmaf(p, r2,  8.3333333333333333e-3f);
    p = fmaf(p, r2, -1.6666666666666667e-1f);
    const float sp = fmaf(r * r2, p, r);
    float qq = 2.0876756987868099e-9f;
    qq = fmaf(qq, r2, -2.7557319223985888e-7f);
    qq = fmaf(qq, r2,  2.4801587301587302e-5f);
    qq = fmaf(qq, r2, -1.3888888888888889e-3f);
    qq = fmaf(qq, r2,  4.1666666666666664e-2f);
    qq = fmaf(qq, r2, -0.5f);
    const float cp = fmaf(qq, r2, 1.0f);

    float s1 = fmaf(cp,  rl, sp);
    float c1 = fmaf(-sp, rl, cp);
    const float sg = (q & 1) ? -1.0f : 1.0f;
    s1 *= sg; c1 *= sg;

    const float s2v = 2.0f * s1 * c1;
    const float c2v = fmaf(-2.0f * s1, s1, 1.0f);

    // anti-alias cutoff: largest k with fl(f0*k) < 22050 (kc >= 45 for f0<480)
    int kc = (int)(22050.0f / f0v);
    if (kc > 64) kc = 64;
    while (kc > 0  && __fmul_rn(f0v, (float)kc)     >= 22050.0f) --kc;
    while (kc < 64 && __fmul_rn(f0v, (float)(kc+1)) <  22050.0f) ++kc;

    const __half2* myH = (const __half2*)(sHh + tid * HSTR);  // pair m: k=2m+1,2m+2
    const float ta = sTA[tid];

    u64 S   = pack2(s1,  s2v);
    u64 C   = pack2(c1,  c2v);
    const u64 S2  = pack2(s2v,  s2v);
    const u64 C2  = pack2(c2v,  c2v);
    const u64 NS2 = pack2(-s2v, -s2v);
    const u64 TH  = pack2(theta,  theta);
    const u64 NTH = pack2(-theta, -theta);
    const u64 TWO = pack2(2.0f, 2.0f);
    u64 KF  = pack2(1.0f, 2.0f);
    u64 acc2 = pack2(0.0f, 0.0f);
    u64 sum2 = pack2(0.0f, 0.0f);

    // pairs m=0..21: k=1..44, never masked
    #pragma unroll
    for (int m = 0; m < 22; ++m){
        float2 hf = __half22float2(myH[m]);
        u64 h2 = pack2(hf.x, hf.y);
        sum2 = add2(sum2, h2);

        u64 a2  = mul2(TH, KF);
        u64 er2 = fma2(NTH, KF, a2);
        u64 sv2 = fma2(C, er2, S);      // sin(fl(k*theta)) ~= s + c*e
        acc2 = fma2(h2, sv2, acc2);

        u64 Sn = fma2(C, S2, mul2(S, C2));
        u64 Cn = fma2(S, NS2, mul2(C, C2));
        S = Sn; C = Cn;
        KF = add2(KF, TWO);
    }

    // pairs m=22..31: k=45..64, masked against kc
    #pragma unroll
    for (int m = 22; m < 32; ++m){
        const int kA = 2*m + 1;
        float2 hf = __half22float2(myH[m]);
        float mA = (kA     <= kc) ? hf.x : 0.0f;
        float mB = (kA + 1 <= kc) ? hf.y : 0.0f;
        u64 m2 = pack2(mA, mB);
        sum2 = add2(sum2, m2);

        u64 a2  = mul2(TH, KF);
        u64 er2 = fma2(NTH, KF, a2);
        u64 sv2 = fma2(C, er2, S);
        acc2 = fma2(m2, sv2, acc2);

        u64 Sn = fma2(C, S2, mul2(S, C2));
        u64 Cn = fma2(S, NS2, mul2(C, C2));
        S = Sn; C = Cn;
        KF = add2(KF, TWO);
    }

    float aA, aB, smA, smB;
    unpack2(acc2, aA, aB);
    unpack2(sum2, smA, smB);
    out[idx] = (aA + aB) * (ta / ((smA + smB) + 1e-5f));
}

extern "C" void kernel_launch(void* const* d_in, const int* in_sizes, int n_in,
                              void* d_out, int out_size)
{
    const float* f0    = (const float*)d_in[0];
    const float* amps  = (const float*)d_in[1];
    const float* phase = (const float*)d_in[2];
    float* out = (float*)d_out;

    scan_kernel<<<BS, 512>>>(f0);
    osc_kernel<<<(BS * NSAMP) / TPB, TPB>>>(f0, amps, phase, out);
}

// round 12
// speedup vs baseline: 1.6623x; 1.6623x over previous
#include <cuda_runtime.h>
#include <cuda_fp16.h>
#include <math.h>

#define BS 32
#define NSAMP 64000
#define NTOT (BS*NSAMP)
#define TPB 128
#define BLK 16                 // XLA ReduceWindowRewriter base_length
#define NB1 (NSAMP/BLK)        // 4000 level-1 blocks per row
#define NB2 (NB1/BLK)          // 250 level-2 blocks
#define NB2P 256               // padded to multiple of 16
#define NB3 (NB2P/BLK)         // 16

__device__ float g_off1[BS*NB1]; // exclusive offset for each level-1 block

typedef unsigned long long u64;

__device__ __forceinline__ float ex2f(float x){ float r; asm("ex2.approx.f32 %0, %1;":"=f"(r):"f"(x)); return r; }
__device__ __forceinline__ float lg2f(float x){ float r; asm("lg2.approx.f32 %0, %1;":"=f"(r):"f"(x)); return r; }

// ---- packed f32x2 helpers ----
__device__ __forceinline__ u64 pack2(float lo, float hi){ u64 r; asm("mov.b64 %0, {%1,%2};":"=l"(r):"f"(lo),"f"(hi)); return r; }
__device__ __forceinline__ void unpack2(u64 v, float& lo, float& hi){ asm("mov.b64 {%0,%1}, %2;":"=f"(lo),"=f"(hi):"l"(v)); }
__device__ __forceinline__ u64 fma2(u64 a,u64 b,u64 c){ u64 r; asm("fma.rn.f32x2 %0,%1,%2,%3;":"=l"(r):"l"(a),"l"(b),"l"(c)); return r; }
__device__ __forceinline__ u64 mul2(u64 a,u64 b){ u64 r; asm("mul.rn.f32x2 %0,%1,%2;":"=l"(r):"l"(a),"l"(b)); return r; }
__device__ __forceinline__ u64 add2(u64 a,u64 b){ u64 r; asm("add.rn.f32x2 %0,%1,%2;":"=l"(r):"l"(a),"l"(b)); return r; }

// pack two f32 into a half2 register in one cvt
__device__ __forceinline__ unsigned int f2h2(float a, float b){
    unsigned int r; asm("cvt.rn.f16x2.f32 %0, %2, %1;":"=r"(r):"f"(a),"f"(b)); return r;
}

// 2*sigmoid(x)^ln(10) + 1e-7
__device__ __forceinline__ float hfun(float x){
    float e = ex2f(-1.4426950408889634f * x);
    float u = lg2f(1.0f + e);
    return fmaf(2.0f, ex2f(-2.3025850929940457f * u), 1e-7f);
}

// increment: fast-math (arcp) form
__device__ __forceinline__ float incr(float f){
    const float RINV = 1.0f / 44100.0f;
    return __fmul_rn(__fmul_rn(6.283185307179586f, f), RINV);
}

// ---------------------------------------------------------------------------
// Fused scan kernel (unchanged, bit-exact): S1 -> I2 -> I3 -> O4 -> off1
// ---------------------------------------------------------------------------
__global__ void __launch_bounds__(512) scan_kernel(const float* __restrict__ f0){
    __shared__ float sI2[NB1];
    __shared__ float sI3[NB2P];
    __shared__ float sO4[NB3];
    const int row = blockIdx.x, tid = threadIdx.x;
    const float* fr = f0 + (size_t)row * NSAMP;

    for (int j = tid; j < NB1; j += 512){
        const float4* fp = (const float4*)(fr + (size_t)j * BLK);
        float acc = 0.0f;
        #pragma unroll
        for (int i = 0; i < BLK/4; i++){
            float4 v = fp[i];
            float d0 = incr(v.x), d1 = incr(v.y), d2 = incr(v.z), d3 = incr(v.w);
            acc = (i == 0) ? d0 : __fadd_rn(acc, d0);
            acc = __fadd_rn(acc, d1);
            acc = __fadd_rn(acc, d2);
            acc = __fadd_rn(acc, d3);
        }
        sI2[j] = acc;
    }
    __syncthreads();

    if (tid < NB2){
        int b = tid * BLK;
        float acc = sI2[b];
        #pragma unroll
        for (int i = 1; i < BLK; i++){ acc = __fadd_rn(acc, sI2[b+i]); sI2[b+i] = acc; }
    }
    __syncthreads();

    if (tid < NB3){
        int b = tid * BLK;
        float acc = 0.0f;
        #pragma unroll
        for (int i = 0; i < BLK; i++){
            int m = b + i;
            float s2 = (m < NB2) ? sI2[m*BLK + (BLK-1)] : 0.0f;
            acc = (i == 0) ? s2 : __fadd_rn(acc, s2);
            sI3[m] = acc;
        }
    }
    __syncthreads();

    if (tid == 0){
        float acc = 0.0f;
        #pragma unroll
        for (int p = 0; p < NB3; p++){
            float s3 = sI3[p*BLK + (BLK-1)];
            acc = (p == 0) ? s3 : __fadd_rn(acc, s3);
            sO4[p] = acc;
        }
    }
    __syncthreads();

    float* off1 = g_off1 + row * NB1;
    for (int j = tid; j < NB1; j += 512){
        float v;
        if (j == 0) v = 0.0f;
        else {
            int jm = j - 1, q = jm >> 4;
            float o3e;
            if (q == 0) o3e = 0.0f;
            else {
                int qm = q - 1, p = qm >> 4;
                float o4e = (p == 0) ? 0.0f : sO4[p-1];
                o3e = __fadd_rn(o4e, sI3[qm]);
            }
            v = __fadd_rn(o3e, sI2[jm]);
        }
        off1[j] = v;
    }
}

// ---------------------------------------------------------------------------
// Oscillator: raw amps staged to smem as fp16 (LINEAR layout, straight cvt on
// the float4 stream — no index math). hfun in-loop, batched 8. 8 CTAs/SM.
// ---------------------------------------------------------------------------
__global__ void __launch_bounds__(TPB, 8) osc_kernel(
    const float* __restrict__ f0,
    const float* __restrict__ amps,
    const float* __restrict__ phase,
    float* __restrict__ out)
{
    __shared__ __half sX[TPB * 65];    // raw amps, linear (mirrors gmem)
    __shared__ float  sD[TPB];
    __shared__ float  sOFF[TPB / BLK];
    const int tid    = threadIdx.x;
    const int nchunk = NSAMP / TPB;
    const int b      = blockIdx.x / nchunk;
    const int t0     = (blockIdx.x % nchunk) * TPB;
    const int sbase  = b * NSAMP + t0;

    {   // float4 staging -> 2x cvt.f16x2 -> one 8B store; pure linear
        const float4* gsrc = (const float4*)(amps + (size_t)sbase * 65);
        uint2* sdst = (uint2*)sX;
        #pragma unroll 4
        for (int i = tid; i < TPB * 65 / 4; i += TPB){
            float4 v = gsrc[i];
            uint2 hp;
            hp.x = f2h2(v.x, v.y);
            hp.y = f2h2(v.z, v.w);
            sdst[i] = hp;
        }
    }
    const int idx   = sbase + tid;
    const float f0v = f0[idx];
    sD[tid] = incr(f0v);
    if (tid < TPB / BLK) sOFF[tid] = g_off1[(sbase >> 4) + tid];
    __syncthreads();

    // bit-exact omega/theta (within-16 ascending fold + one offset add)
    const int g = tid >> 4, i15 = tid & 15;
    float inc = sD[g * BLK];
    for (int i = 1; i <= i15; ++i) inc = __fadd_rn(inc, sD[g * BLK + i]);
    const float omega = __fadd_rn(sOFF[g], inc);
    const float theta = __fadd_rn(omega, phase[b]);

    // accurate sincos(theta): mod-pi in double
    const double thd = (double)theta;
    const double qd  = rint(thd * 0.31830988618379067154);
    const int    q   = (int)qd;
    const double rd  = fma(-3.14159265358979323846, qd, thd);
    const float  r   = (float)rd;
    const float  rl  = (float)(rd - (double)r);

    const float r2 = r * r;
    float p = -2.5052108385441718e-8f;
    p = fmaf(p, r2,  2.7557319223985893e-6f);
    p = fmaf(p, r2, -1.9841269841269841e-4f);
    p = fmaf(p, r2,  8.3333333333333333e-3f);
    p = fmaf(p, r2, -1.6666666666666667e-1f);
    const float sp = fmaf(r * r2, p, r);
    float qq = 2.0876756987868099e-9f;
    qq = fmaf(qq, r2, -2.7557319223985888e-7f);
    qq = fmaf(qq, r2,  2.4801587301587302e-5f);
    qq = fmaf(qq, r2, -1.3888888888888889e-3f);
    qq = fmaf(qq, r2,  4.1666666666666664e-2f);
    qq = fmaf(qq, r2, -0.5f);
    const float cp = fmaf(qq, r2, 1.0f);

    float s1 = fmaf(cp,  rl, sp);
    float c1 = fmaf(-sp, rl, cp);
    const float sg = (q & 1) ? -1.0f : 1.0f;
    s1 *= sg; c1 *= sg;

    const float s2v = 2.0f * s1 * c1;
    const float c2v = fmaf(-2.0f * s1, s1, 1.0f);

    // anti-alias cutoff: largest k with fl(f0*k) < 22050 (kc >= 45 for f0<480)
    int kc = (int)(22050.0f / f0v);
    if (kc > 64) kc = 64;
    while (kc > 0  && __fmul_rn(f0v, (float)kc)     >= 22050.0f) --kc;
    while (kc < 64 && __fmul_rn(f0v, (float)(kc+1)) <  22050.0f) ++kc;

    const __half* my = sX + tid * 65;  // my[0]=raw ta input, my[k]=raw h input
    const float ta = hfun(__half2float(my[0]));

    u64 S   = pack2(s1,  s2v);
    u64 C   = pack2(c1,  c2v);
    const u64 S2  = pack2(s2v,  s2v);
    const u64 C2  = pack2(c2v,  c2v);
    const u64 NS2 = pack2(-s2v, -s2v);
    const u64 TH  = pack2(theta,  theta);
    const u64 NTH = pack2(-theta, -theta);
    const u64 TWO = pack2(2.0f, 2.0f);
    u64 KF  = pack2(1.0f, 2.0f);
    u64 acc2 = pack2(0.0f, 0.0f);
    u64 sum2 = pack2(0.0f, 0.0f);

    // 8 groups of 8 harmonics; batch hfun over 8 for MUFU ILP.
    // Groups 0..4 cover k=1..40 (< 45) -> never masked.
    #pragma unroll
    for (int gb = 0; gb < 8; ++gb){
        float h[8];
        #pragma unroll
        for (int i = 0; i < 8; ++i)
            h[i] = hfun(__half2float(my[gb*8 + 1 + i]));

        #pragma unroll
        for (int jj = 0; jj < 4; ++jj){
            const int kA = gb*8 + 2*jj + 1;
            float hA = h[2*jj], hB = h[2*jj+1];
            if (gb >= 5){                       // masking only possible here
                hA = (kA     <= kc) ? hA : 0.0f;
                hB = (kA + 1 <= kc) ? hB : 0.0f;
            }
            u64 h2 = pack2(hA, hB);
            sum2 = add2(sum2, h2);

            u64 a2  = mul2(TH, KF);
            u64 er2 = fma2(NTH, KF, a2);
            u64 sv2 = fma2(C, er2, S);      // sin(fl(k*theta)) ~= s + c*e
            acc2 = fma2(h2, sv2, acc2);

            u64 Sn = fma2(C, S2, mul2(S, C2));
            u64 Cn = fma2(S, NS2, mul2(C, C2));
            S = Sn; C = Cn;
            KF = add2(KF, TWO);
        }
    }

    float aA, aB, smA, smB;
    unpack2(acc2, aA, aB);
    unpack2(sum2, smA, smB);
    out[idx] = (aA + aB) * (ta / ((smA + smB) + 1e-5f));
}

extern "C" void kernel_launch(void* const* d_in, const int* in_sizes, int n_in,
                              void* d_out, int out_size)
{
    const float* f0    = (const float*)d_in[0];
    const float* amps  = (const float*)d_in[1];
    const float* phase = (const float*)d_in[2];
    float* out = (float*)d_out;

    scan_kernel<<<BS, 512>>>(f0);
    osc_kernel<<<(BS * NSAMP) / TPB, TPB>>>(f0, amps, phase, out);
}

// round 13
// speedup vs baseline: 1.6627x; 1.0002x over previous
#include <cuda_runtime.h>
#include <cuda_fp16.h>
#include <math.h>

#define BS 32
#define NSAMP 64000
#define NTOT (BS*NSAMP)
#define TPB 128
#define BLK 16                 // XLA ReduceWindowRewriter base_length
#define NB1 (NSAMP/BLK)        // 4000 level-1 blocks per row
#define NB2 (NB1/BLK)          // 250 level-2 blocks
#define NB2P 256               // padded to multiple of 16
#define NB3 (NB2P/BLK)         // 16

__device__ float g_S1[BS*NB1];   // level-1 block sums
__device__ float g_off1[BS*NB1]; // exclusive offset for each level-1 block

typedef unsigned long long u64;

__device__ __forceinline__ float ex2f(float x){ float r; asm("ex2.approx.f32 %0, %1;":"=f"(r):"f"(x)); return r; }
__device__ __forceinline__ float lg2f(float x){ float r; asm("lg2.approx.f32 %0, %1;":"=f"(r):"f"(x)); return r; }

// ---- packed f32x2 helpers ----
__device__ __forceinline__ u64 pack2(float lo, float hi){ u64 r; asm("mov.b64 %0, {%1,%2};":"=l"(r):"f"(lo),"f"(hi)); return r; }
__device__ __forceinline__ void unpack2(u64 v, float& lo, float& hi){ asm("mov.b64 {%0,%1}, %2;":"=f"(lo),"=f"(hi):"l"(v)); }
__device__ __forceinline__ u64 fma2(u64 a,u64 b,u64 c){ u64 r; asm("fma.rn.f32x2 %0,%1,%2,%3;":"=l"(r):"l"(a),"l"(b),"l"(c)); return r; }
__device__ __forceinline__ u64 mul2(u64 a,u64 b){ u64 r; asm("mul.rn.f32x2 %0,%1,%2;":"=l"(r):"l"(a),"l"(b)); return r; }
__device__ __forceinline__ u64 add2(u64 a,u64 b){ u64 r; asm("add.rn.f32x2 %0,%1,%2;":"=l"(r):"l"(a),"l"(b)); return r; }

// pack two f32 into a half2 register in one cvt
__device__ __forceinline__ unsigned int f2h2(float a, float b){
    unsigned int r; asm("cvt.rn.f16x2.f32 %0, %2, %1;":"=r"(r):"f"(a),"f"(b)); return r;
}

// 2*sigmoid(x)^ln10 (merged tail: 2*2^(-ln10*u) == 2^(1-ln10*u); +1e-7 dropped,
// error <= 1e-7 abs -> ~1e-6 output)
__device__ __forceinline__ float hfast(float x){
    float e = ex2f(-1.4426950408889634f * x);
    float u = lg2f(1.0f + e);
    return ex2f(fmaf(u, -2.3025850929940457f, 1.0f));
}
// full-precision variant for total_amplitude (keeps +1e-7; ta can be tiny)
__device__ __forceinline__ float hfull(float x){
    float e = ex2f(-1.4426950408889634f * x);
    float u = lg2f(1.0f + e);
    return fmaf(2.0f, ex2f(-2.3025850929940457f * u), 1e-7f);
}

// increment: fast-math (arcp) form
__device__ __forceinline__ float incr(float f){
    const float RINV = 1.0f / 44100.0f;
    return __fmul_rn(__fmul_rn(6.283185307179586f, f), RINV);
}

// ---------------------------------------------------------------------------
// Kernel A (full grid): level-1 block sums S1 (ascending fold within 16-block)
// ---------------------------------------------------------------------------
__global__ void __launch_bounds__(TPB) prep_kernel(const float* __restrict__ f0){
    int j = blockIdx.x * blockDim.x + threadIdx.x;
    if (j >= BS * NB1) return;
    const float4* fp = (const float4*)(f0 + (size_t)j * BLK);
    float acc = 0.0f;
    #pragma unroll
    for (int i = 0; i < BLK/4; i++){
        float4 v = fp[i];
        float d0 = incr(v.x), d1 = incr(v.y), d2 = incr(v.z), d3 = incr(v.w);
        acc = (i == 0) ? d0 : __fadd_rn(acc, d0);
        acc = __fadd_rn(acc, d1);
        acc = __fadd_rn(acc, d2);
        acc = __fadd_rn(acc, d3);
    }
    g_S1[j] = acc;
}

// ---------------------------------------------------------------------------
// Kernel B (32 blocks): recursive 16-ary blocked scan of S1 -> off1 offsets
// ---------------------------------------------------------------------------
__global__ void __launch_bounds__(256) offsets_kernel(){
    __shared__ float sI2[NB1];
    __shared__ float sI3[NB2P];
    __shared__ float sO4[NB3];
    const int row = blockIdx.x, tid = threadIdx.x, nt = 256;
    const float* S1 = g_S1 + row * NB1;
    for (int i = tid; i < NB1; i += nt) sI2[i] = S1[i];
    __syncthreads();

    if (tid < NB2){
        int b = tid * BLK;
        float acc = sI2[b];
        #pragma unroll
        for (int i = 1; i < BLK; i++){ acc = __fadd_rn(acc, sI2[b+i]); sI2[b+i] = acc; }
    }
    __syncthreads();

    if (tid < NB3){
        int b = tid * BLK;
        float acc = 0.0f;
        #pragma unroll
        for (int i = 0; i < BLK; i++){
            int m = b + i;
            float s2 = (m < NB2) ? sI2[m*BLK + (BLK-1)] : 0.0f;
            acc = (i == 0) ? s2 : __fadd_rn(acc, s2);
            sI3[m] = acc;
        }
    }
    __syncthreads();

    if (tid == 0){
        float acc = 0.0f;
        #pragma unroll
        for (int p = 0; p < NB3; p++){
            float s3 = sI3[p*BLK + (BLK-1)];
            acc = (p == 0) ? s3 : __fadd_rn(acc, s3);
            sO4[p] = acc;
        }
    }
    __syncthreads();

    float* off1 = g_off1 + row * NB1;
    for (int j = tid; j < NB1; j += nt){
        float v;
        if (j == 0) v = 0.0f;
        else {
            int jm = j - 1, q = jm >> 4;
            float o3e;
            if (q == 0) o3e = 0.0f;
            else {
                int qm = q - 1, p = qm >> 4;
                float o4e = (p == 0) ? 0.0f : sO4[p-1];
                o3e = __fadd_rn(o4e, sI3[qm]);
            }
            v = __fadd_rn(o3e, sI2[jm]);
        }
        off1[j] = v;
    }
}

// ---------------------------------------------------------------------------
// Oscillator: fp16 raw-amp staging (STS.128), hfast in-loop (batch 8),
// packed rotation + fl(theta*k) correction; 9 CTAs/SM.
// ---------------------------------------------------------------------------
__global__ void __launch_bounds__(TPB, 9) osc_kernel(
    const float* __restrict__ f0,
    const float* __restrict__ amps,
    const float* __restrict__ phase,
    float* __restrict__ out)
{
    __shared__ __half sX[TPB * 65];    // raw amps, linear (mirrors gmem)
    __shared__ float  sD[TPB];
    __shared__ float  sOFF[TPB / BLK];
    const int tid    = threadIdx.x;
    const int nchunk = NSAMP / TPB;
    const int b      = blockIdx.x / nchunk;
    const int t0     = (blockIdx.x % nchunk) * TPB;
    const int sbase  = b * NSAMP + t0;

    {   // stage 8 floats/iter: 2x LDG.128 -> 4x cvt.f16x2 -> 1x STS.128
        const float4* gsrc = (const float4*)(amps + (size_t)sbase * 65);
        uint4* sdst = (uint4*)sX;
        #pragma unroll 3
        for (int i = tid; i < TPB * 65 / 8; i += TPB){
            float4 a = gsrc[2*i], c = gsrc[2*i+1];
            uint4 hp;
            hp.x = f2h2(a.x, a.y);
            hp.y = f2h2(a.z, a.w);
            hp.z = f2h2(c.x, c.y);
            hp.w = f2h2(c.z, c.w);
            sdst[i] = hp;
        }
    }
    const int idx   = sbase + tid;
    const float f0v = f0[idx];
    sD[tid] = incr(f0v);
    if (tid < TPB / BLK) sOFF[tid] = g_off1[(sbase >> 4) + tid];
    __syncthreads();

    // bit-exact omega/theta (within-16 ascending fold + one offset add)
    const int g = tid >> 4, i15 = tid & 15;
    float inc = sD[g * BLK];
    for (int i = 1; i <= i15; ++i) inc = __fadd_rn(inc, sD[g * BLK + i]);
    const float omega = __fadd_rn(sOFF[g], inc);
    const float theta = __fadd_rn(omega, phase[b]);

    // accurate sincos(theta): mod-pi in double
    const double thd = (double)theta;
    const double qd  = rint(thd * 0.31830988618379067154);
    const int    q   = (int)qd;
    const double rd  = fma(-3.14159265358979323846, qd, thd);
    const float  r   = (float)rd;
    const float  rl  = (float)(rd - (double)r);

    const float r2 = r * r;
    float p = -2.5052108385441718e-8f;
    p = fmaf(p, r2,  2.7557319223985893e-6f);
    p = fmaf(p, r2, -1.9841269841269841e-4f);
    p = fmaf(p, r2,  8.3333333333333333e-3f);
    p = fmaf(p, r2, -1.6666666666666667e-1f);
    const float sp = fmaf(r * r2, p, r);
    float qq = 2.0876756987868099e-9f;
    qq = fmaf(qq, r2, -2.7557319223985888e-7f);
    qq = fmaf(qq, r2,  2.4801587301587302e-5f);
    qq = fmaf(qq, r2, -1.3888888888888889e-3f);
    qq = fmaf(qq, r2,  4.1666666666666664e-2f);
    qq = fmaf(qq, r2, -0.5f);
    const float cp = fmaf(qq, r2, 1.0f);

    float s1 = fmaf(cp,  rl, sp);
    float c1 = fmaf(-sp, rl, cp);
    const float sg = (q & 1) ? -1.0f : 1.0f;
    s1 *= sg; c1 *= sg;

    const float s2v = 2.0f * s1 * c1;
    const float c2v = fmaf(-2.0f * s1, s1, 1.0f);

    // branchless anti-alias cutoff: largest k with fl(f0*k) < 22050.
    // __fdividef is within 1 ulp -> candidate off by at most 1; two predicated
    // fixups restore the exact fp32-compare boundary, then clamp to 64.
    int kc = (int)__fdividef(22050.0f, f0v);
    kc += (__fmul_rn(f0v, (float)(kc+1)) <  22050.0f) ? 1 : 0;
    kc -= (__fmul_rn(f0v, (float)kc)     >= 22050.0f) ? 1 : 0;
    kc = (kc > 64) ? 64 : kc;

    const __half* my = sX + tid * 65;  // my[0]=raw ta input, my[k]=raw h input
    const float ta = hfull(__half2float(my[0]));

    u64 S   = pack2(s1,  s2v);
    u64 C   = pack2(c1,  c2v);
    const u64 S2  = pack2(s2v,  s2v);
    const u64 C2  = pack2(c2v,  c2v);
    const u64 NS2 = pack2(-s2v, -s2v);
    const u64 TH  = pack2(theta,  theta);
    const u64 NTH = pack2(-theta, -theta);
    const u64 TWO = pack2(2.0f, 2.0f);
    u64 KF  = pack2(1.0f, 2.0f);
    u64 acc2 = pack2(0.0f, 0.0f);
    u64 sum2 = pack2(0.0f, 0.0f);

    // 8 groups of 8 harmonics; batch hfast over 8 for MUFU ILP.
    // Groups 0..4 cover k=1..40 (< 45) -> never masked.
    #pragma unroll
    for (int gb = 0; gb < 8; ++gb){
        float h[8];
        #pragma unroll
        for (int i = 0; i < 8; ++i)
            h[i] = hfast(__half2float(my[gb*8 + 1 + i]));

        #pragma unroll
        for (int jj = 0; jj < 4; ++jj){
            const int kA = gb*8 + 2*jj + 1;
            float hA = h[2*jj], hB = h[2*jj+1];
            if (gb >= 5){                       // masking only possible here
                hA = (kA     <= kc) ? hA : 0.0f;
                hB = (kA + 1 <= kc) ? hB : 0.0f;
            }
            u64 h2 = pack2(hA, hB);
            sum2 = add2(sum2, h2);

            u64 a2  = mul2(TH, KF);
            u64 er2 = fma2(NTH, KF, a2);
            u64 sv2 = fma2(C, er2, S);      // sin(fl(k*theta)) ~= s + c*e
            acc2 = fma2(h2, sv2, acc2);

            u64 Sn = fma2(C, S2, mul2(S, C2));
            u64 Cn = fma2(S, NS2, mul2(C, C2));
            S = Sn; C = Cn;
            KF = add2(KF, TWO);
        }
    }

    float aA, aB, smA, smB;
    unpack2(acc2, aA, aB);
    unpack2(sum2, smA, smB);
    out[idx] = (aA + aB) * (ta / ((smA + smB) + 1e-5f));
}

extern "C" void kernel_launch(void* const* d_in, const int* in_sizes, int n_in,
                              void* d_out, int out_size)
{
    const float* f0    = (const float*)d_in[0];
    const float* amps  = (const float*)d_in[1];
    const float* phase = (const float*)d_in[2];
    float* out = (float*)d_out;

    prep_kernel<<<(BS*NB1)/TPB, TPB>>>(f0);
    offsets_kernel<<<BS, 256>>>();
    osc_kernel<<<(BS * NSAMP) / TPB, TPB>>>(f0, amps, phase, out);
}